// round 16
// baseline (speedup 1.0000x reference)
#include <cuda_runtime.h>
#include <cuda_fp16.h>
#include <cstdint>
#include <math.h>

#define TGT   2048
#define NBSZ  2
#define EMB   1024
#define NH    16
#define HD    64
#define NBH   (NBSZ*NH)      // 32
#define MROWS (TGT*NBSZ)     // 4096
#define NCH   (TGT/64)       // 32 flash chunks

// ---------------- scratch (device globals) ----------------------------------
static __device__ __half g_Qh [(size_t)NBH*TGT*HD];
static __device__ __half g_Kh [(size_t)NBH*TGT*HD];
static __device__ __half g_Vh [(size_t)NBH*TGT*HD];     // [bh][t][d] row-major
static __device__ __half g_attnh[(size_t)MROWS*EMB];
static __device__ __half g_Ph [(size_t)NBH*TGT*TGT];    // P = e^(S-m_run), fp16
static __device__ float  g_mrun [(size_t)NBH*NCH*TGT];  // m_run * log2e
static __device__ float  g_statx[(size_t)NBH*TGT];      // m_fin*log2e - log2(invl)
static __device__ __half g_qh [(size_t)MROWS*EMB];
static __device__ __half g_wih[(size_t)3*EMB*EMB];
static __device__ __half g_woh[(size_t)EMB*EMB];

// ---------------- helpers ---------------------------------------------------
__device__ __forceinline__ uint32_t pack_h2(float hi, float lo){
    uint32_t r; asm("cvt.rn.f16x2.f32 %0, %1, %2;" : "=r"(r) : "f"(hi), "f"(lo));
    return r;
}
__device__ __forceinline__ void mma16h(float* c, const uint32_t* a, const uint32_t* b){
    asm volatile("mma.sync.aligned.m16n8k16.row.col.f32.f16.f16.f32 "
        "{%0,%1,%2,%3}, {%4,%5,%6,%7}, {%8,%9}, {%0,%1,%2,%3};"
        : "+f"(c[0]), "+f"(c[1]), "+f"(c[2]), "+f"(c[3])
        : "r"(a[0]), "r"(a[1]), "r"(a[2]), "r"(a[3]), "r"(b[0]), "r"(b[1]));
}
__device__ __forceinline__ void ldsm4(uint32_t& r0, uint32_t& r1, uint32_t& r2,
                                      uint32_t& r3, uint32_t addr){
    asm volatile("ldmatrix.sync.aligned.m8n8.x4.shared.b16 {%0,%1,%2,%3}, [%4];"
        : "=r"(r0), "=r"(r1), "=r"(r2), "=r"(r3) : "r"(addr));
}
__device__ __forceinline__ void ldsm4t(uint32_t& r0, uint32_t& r1, uint32_t& r2,
                                       uint32_t& r3, uint32_t addr){
    asm volatile("ldmatrix.sync.aligned.m8n8.x4.trans.shared.b16 {%0,%1,%2,%3}, [%4];"
        : "=r"(r0), "=r"(r1), "=r"(r2), "=r"(r3) : "r"(addr));
}
__device__ __forceinline__ uint32_t smem_u32(const void* p){
    uint32_t a; asm("{ .reg .u64 t; cvta.to.shared.u64 t, %1; cvt.u32.u64 %0, t; }":"=r"(a):"l"(p));
    return a;
}
__device__ __forceinline__ void cpa16(uint32_t s, const void* g){
    asm volatile("cp.async.cg.shared.global [%0], [%1], 16;" :: "r"(s), "l"(g) : "memory");
}
#define CP_COMMIT() asm volatile("cp.async.commit_group;" ::: "memory")
#define CP_WAIT(n)  asm volatile("cp.async.wait_group %0;" :: "n"(n) : "memory")

#define LDSM_H_A(j, rowbase, stride) \
    ((((rowbase) + (((j)>>3)&1)*8 + ((j)&7))*(stride)) + (((j)>>4)*8))
#define LDSM_H_B(j, rowbase, stride) \
    ((((rowbase) + (((j)>>4)*8) + ((j)&7))*(stride)) + ((((j)>>3)&1)*8))

#define L2E 1.4426950408889634f

// ---------------- fused pre-convert fp32 -> fp16 ----------------------------
__global__ void preconv_all_k(const float4* __restrict__ q,
                              const float4* __restrict__ wi,
                              const float4* __restrict__ wo,
                              uint2* __restrict__ dq,
                              uint2* __restrict__ dwi,
                              uint2* __restrict__ dwo)
{
    const int NQ = MROWS*EMB/4, NWI = 3*EMB*EMB/4, NWO = EMB*EMB/4;
    int i = blockIdx.x*blockDim.x + threadIdx.x;
    float4 v; uint2 o;
    if (i < NQ)              { v = q[i];        o.x = pack_h2(v.y, v.x); o.y = pack_h2(v.w, v.z); dq[i] = o; }
    else if (i < NQ+NWI)     { v = wi[i-NQ];    o.x = pack_h2(v.y, v.x); o.y = pack_h2(v.w, v.z); dwi[i-NQ] = o; }
    else if (i < NQ+NWI+NWO) { v = wo[i-NQ-NWI];o.x = pack_h2(v.y, v.x); o.y = pack_h2(v.w, v.z); dwo[i-NQ-NWI] = o; }
}

// ===========================================================================
// QKV GEMM (fp16): block 128x128, 256 thr, warp 64x32, BK=64, 3-stage ring.
// ===========================================================================
#define GEMM_SMEM_BYTES (3*18432*2)   // 110592

__global__ __launch_bounds__(256, 2)
void qkv_gemm(const float* __restrict__ biasg)
{
    constexpr int KC = 16;
    extern __shared__ char smc[];
    const uint32_t sb = smem_u32(smc);
    const int tid = threadIdx.x, lane = tid & 31, wid = tid >> 5;
    const int wm = wid & 1, wn = wid >> 1;
    const int lr = lane >> 2, lc = lane & 3;
    const int bm = blockIdx.y * 128, bn = blockIdx.x * 128;

    const __half* A = g_qh;
    const __half* B = g_wih;

    const uint32_t aoff = LDSM_H_A(lane, wm*64, 72);
    const uint32_t boff = LDSM_H_B(lane, wn*32, 72);

    float acc[4][4][4];
    #pragma unroll
    for (int i=0;i<4;i++) for (int j=0;j<4;j++) for (int k=0;k<4;k++) acc[i][j][k]=0.f;

    auto issue = [&](int c){
        const int k0 = c*64, st = c % 3;
        const uint32_t ab = sb + st*36864;
        const uint32_t bb = ab + 18432;
        #pragma unroll
        for (int i=0;i<4;i++){
            int fi = tid + i*256, r = fi>>3, c8 = fi&7;
            cpa16(ab + (r*72 + c8*8)*2, A + (size_t)(bm+r)*EMB + k0 + c8*8);
            cpa16(bb + (r*72 + c8*8)*2, B + (size_t)(bn+r)*EMB + k0 + c8*8);
        }
        CP_COMMIT();
    };

    issue(0); issue(1);
    for (int c = 0; c < KC; c++) {
        if (c + 1 < KC) { CP_WAIT(1); } else { CP_WAIT(0); }
        __syncthreads();
        if (c + 2 < KC) issue(c+2);
        const int st = c % 3;
        const uint32_t Ab = sb + st*36864;
        const uint32_t Bb = Ab + 18432;
        #pragma unroll
        for (int ks = 0; ks < 4; ks++) {
            uint32_t af[4][4], bf[4][2];
            #pragma unroll
            for (int mt=0; mt<4; mt++)
                ldsm4(af[mt][0], af[mt][1], af[mt][2], af[mt][3],
                      Ab + (aoff + mt*16*72 + ks*16)*2);
            #pragma unroll
            for (int p=0; p<2; p++)
                ldsm4(bf[2*p][0], bf[2*p][1], bf[2*p+1][0], bf[2*p+1][1],
                      Bb + (boff + p*16*72 + ks*16)*2);
            #pragma unroll
            for (int mt=0; mt<4; mt++)
                #pragma unroll
                for (int nt=0; nt<4; nt++)
                    mma16h(acc[mt][nt], af[mt], bf[nt]);
        }
    }

    float bias0[4], bias1[4];
    #pragma unroll
    for (int nt=0; nt<4; nt++){
        int n = bn + wn*32 + nt*8 + lc*2;
        bias0[nt] = biasg[n]; bias1[nt] = biasg[n+1];
    }

    #pragma unroll
    for (int mt=0; mt<4; mt++)
    #pragma unroll
    for (int hf=0; hf<2; hf++){
        const int m = bm + wm*64 + mt*16 + hf*8 + lr;
        const int t = m >> 1, b = m & 1;
        #pragma unroll
        for (int nt=0; nt<4; nt++){
            const int n = bn + wn*32 + nt*8 + lc*2;
            float v0 = acc[mt][nt][hf*2+0] + bias0[nt];
            float v1 = acc[mt][nt][hf*2+1] + bias1[nt];
            const int which = n >> 10, e = n & 1023, h = e >> 6, d = e & 63;
            const int bh = b*NH + h;
            if (which == 0) {
                *(uint32_t*)&g_Qh[((size_t)bh*TGT + t)*HD + d] =
                    pack_h2(v1*0.125f, v0*0.125f);
            } else if (which == 1) {
                *(uint32_t*)&g_Kh[((size_t)bh*TGT + t)*HD + d] = pack_h2(v1, v0);
            } else {
                *(uint32_t*)&g_Vh[((size_t)bh*TGT + t)*HD + d] = pack_h2(v1, v0);
            }
        }
    }
}

// ===========================================================================
// Flash attention (fp16) + P store: 256 thr, q-tile 128, k-chunk 64, 4-stage.
// ===========================================================================
#define FA_SMEM_BYTES (5*18432)

__global__ __launch_bounds__(256, 2)
void flash_attn_k()
{
    constexpr int NC = NCH;
    extern __shared__ char smc[];
    const uint32_t sb = smem_u32(smc);
    const int tid = threadIdx.x, lane = tid & 31, w = tid >> 5;
    const int lr = lane >> 2, lc = lane & 3;
    const int qt = blockIdx.x, bh = blockIdx.y;
    const int b = bh >> 4, h = bh & 15;
    const int qbase = qt * 128;

    const __half* Qg = g_Qh + (size_t)bh*TGT*HD;
    const __half* Kg = g_Kh + (size_t)bh*TGT*HD;
    const __half* Vg = g_Vh + (size_t)bh*TGT*HD;

    const uint32_t qoff = LDSM_H_A(lane, w*16, 72);
    const uint32_t koff = LDSM_H_B(lane, 0, 72);
    const uint32_t voff = LDSM_H_A(lane, 0, 72);

    auto issue_kv = [&](int kc){
        const int st = kc & 3;
        const uint32_t kb = sb + 18432 + st*18432;
        const uint32_t vb = kb + 9216;
        #pragma unroll
        for (int i=0;i<2;i++){
            int fi = tid + i*256, r = fi>>3, c8 = fi&7;
            cpa16(kb + (r*72 + c8*8)*2, Kg + (size_t)(kc*64+r)*HD + c8*8);
            cpa16(vb + (r*72 + c8*8)*2, Vg + (size_t)(kc*64+r)*HD + c8*8);
        }
        CP_COMMIT();
    };

    #pragma unroll
    for (int i=0;i<4;i++){
        int fi = tid + i*256, r = fi>>3, c8 = fi&7;
        cpa16(sb + (r*72 + c8*8)*2, Qg + (size_t)(qbase+r)*HD + c8*8);
    }
    {
        const uint32_t kb = sb + 18432, vb = kb + 9216;
        #pragma unroll
        for (int i=0;i<2;i++){
            int fi = tid + i*256, r = fi>>3, c8 = fi&7;
            cpa16(kb + (r*72 + c8*8)*2, Kg + (size_t)r*HD + c8*8);
            cpa16(vb + (r*72 + c8*8)*2, Vg + (size_t)r*HD + c8*8);
        }
        CP_COMMIT();
    }
    issue_kv(1); issue_kv(2);

    float acc_o[8][4];
    #pragma unroll
    for (int j=0;j<8;j++) for (int k=0;k<4;k++) acc_o[j][k]=0.f;
    float m_r[2] = {-1e30f,-1e30f};
    float l_r[2] = {0.f,0.f};

    const unsigned FULL = 0xffffffffu;

    for (int kc = 0; kc < NC; kc++) {
        if (kc + 2 < NC)      { CP_WAIT(2); }
        else if (kc + 1 < NC) { CP_WAIT(1); }
        else                  { CP_WAIT(0); }
        __syncthreads();
        if (kc + 3 < NC) issue_kv(kc + 3);

        const int st = kc & 3;
        const uint32_t KBu = sb + 18432 + st*18432;
        const uint32_t VBu = KBu + 9216;

        float s[8][4];
        #pragma unroll
        for (int j=0;j<8;j++) for (int k=0;k<4;k++) s[j][k]=0.f;
        #pragma unroll
        for (int ks=0; ks<4; ks++){
            uint32_t a[4], bf[8][2];
            ldsm4(a[0], a[1], a[2], a[3], sb + (qoff + ks*16)*2);
            #pragma unroll
            for (int p=0; p<4; p++)
                ldsm4(bf[2*p][0], bf[2*p][1], bf[2*p+1][0], bf[2*p+1][1],
                      KBu + (koff + p*16*72 + ks*16)*2);
            #pragma unroll
            for (int nt=0; nt<8; nt++)
                mma16h(s[nt], a, bf[nt]);
        }

        // online softmax over this 64-col chunk (+ m_run store)
        #pragma unroll
        for (int hf=0; hf<2; hf++){
            float cm = -1e30f;
            #pragma unroll
            for (int nt=0; nt<8; nt++)
                cm = fmaxf(cm, fmaxf(s[nt][hf*2], s[nt][hf*2+1]));
            cm = fmaxf(cm, __shfl_xor_sync(FULL, cm, 1));
            cm = fmaxf(cm, __shfl_xor_sync(FULL, cm, 2));
            const float mn = fmaxf(m_r[hf], cm);
            const float sc = __expf(m_r[hf] - mn);
            float cs = 0.f;
            #pragma unroll
            for (int nt=0; nt<8; nt++){
                float e0 = __expf(s[nt][hf*2]   - mn);
                float e1 = __expf(s[nt][hf*2+1] - mn);
                s[nt][hf*2] = e0; s[nt][hf*2+1] = e1;
                cs += e0 + e1;
            }
            cs += __shfl_xor_sync(FULL, cs, 1);
            cs += __shfl_xor_sync(FULL, cs, 2);
            l_r[hf] = l_r[hf]*sc + cs;
            m_r[hf] = mn;
            #pragma unroll
            for (int nt=0; nt<8; nt++){
                acc_o[nt][hf*2]   *= sc;
                acc_o[nt][hf*2+1] *= sc;
            }
            if (lc == 0)
                g_mrun[((size_t)bh*NCH + kc)*TGT + qbase + w*16 + hf*8 + lr] = mn * L2E;
        }

        // store P chunk (fp16) — same values PV consumes
        #pragma unroll
        for (int hf=0; hf<2; hf++){
            const int row = qbase + w*16 + hf*8 + lr;
            __half* pr = g_Ph + ((size_t)bh*TGT + row)*TGT + kc*64;
            #pragma unroll
            for (int nt=0; nt<8; nt++)
                *(uint32_t*)&pr[nt*8 + lc*2] = pack_h2(s[nt][hf*2+1], s[nt][hf*2]);
        }

        // O += P V
        #pragma unroll
        for (int ks2=0; ks2<4; ks2++){
            uint32_t a[4];
            a[0] = pack_h2(s[2*ks2  ][1], s[2*ks2  ][0]);
            a[1] = pack_h2(s[2*ks2  ][3], s[2*ks2  ][2]);
            a[2] = pack_h2(s[2*ks2+1][1], s[2*ks2+1][0]);
            a[3] = pack_h2(s[2*ks2+1][3], s[2*ks2+1][2]);
            #pragma unroll
            for (int p=0; p<4; p++){
                uint32_t b0, b1, b2, b3;
                ldsm4t(b0, b1, b2, b3, VBu + (voff + ks2*16*72 + p*16)*2);
                uint32_t bA[2] = {b0, b1}, bB[2] = {b2, b3};
                mma16h(acc_o[2*p  ], a, bA);
                mma16h(acc_o[2*p+1], a, bB);
            }
        }
    }

    #pragma unroll
    for (int hf=0; hf<2; hf++){
        const float invl = 1.0f / l_r[hf];
        const int q = qbase + w*16 + hf*8 + lr;
        __half* dst = g_attnh + ((size_t)q*NBSZ + b)*EMB + h*HD;
        #pragma unroll
        for (int nt=0; nt<8; nt++)
            *(uint32_t*)&dst[nt*8 + lc*2] =
                pack_h2(acc_o[nt][hf*2+1]*invl, acc_o[nt][hf*2]*invl);
        if (lc == 0)
            g_statx[(size_t)bh*TGT + q] = m_r[hf]*L2E - __log2f(invl);
    }
}

// ===========================================================================
// Tail: blocks [0,256) out-proj (tensor-bound); [256, 256+4096) avg reduce
// (DRAM-bound). They overlap on disjoint resources.
// ===========================================================================
#define TAIL_SMEM_BYTES (3*18432*2)   // out-proj ring

__device__ __forceinline__ void outproj_body(float* __restrict__ Cg,
                                             const float* __restrict__ biasg, int bid)
{
    constexpr int KC = 16;
    extern __shared__ char smc[];
    const uint32_t sb = smem_u32(smc);
    const int tid = threadIdx.x, lane = tid & 31, wid = tid >> 5;
    const int wm = wid & 1, wn = wid >> 1;
    const int lr = lane >> 2, lc = lane & 3;
    const int bm = (bid >> 3) * 128, bn = (bid & 7) * 128;

    const __half* A = g_attnh;
    const __half* B = g_woh;

    const uint32_t aoff = LDSM_H_A(lane, wm*64, 72);
    const uint32_t boff = LDSM_H_B(lane, wn*32, 72);

    float acc[4][4][4];
    #pragma unroll
    for (int i=0;i<4;i++) for (int j=0;j<4;j++) for (int k=0;k<4;k++) acc[i][j][k]=0.f;

    auto issue = [&](int c){
        const int k0 = c*64, st = c % 3;
        const uint32_t ab = sb + st*36864;
        const uint32_t bb = ab + 18432;
        #pragma unroll
        for (int i=0;i<4;i++){
            int fi = tid + i*256, r = fi>>3, c8 = fi&7;
            cpa16(ab + (r*72 + c8*8)*2, A + (size_t)(bm+r)*EMB + k0 + c8*8);
            cpa16(bb + (r*72 + c8*8)*2, B + (size_t)(bn+r)*EMB + k0 + c8*8);
        }
        CP_COMMIT();
    };

    issue(0); issue(1);
    for (int c = 0; c < KC; c++) {
        if (c + 1 < KC) { CP_WAIT(1); } else { CP_WAIT(0); }
        __syncthreads();
        if (c + 2 < KC) issue(c+2);
        const int st = c % 3;
        const uint32_t Ab = sb + st*36864;
        const uint32_t Bb = Ab + 18432;
        #pragma unroll
        for (int ks = 0; ks < 4; ks++) {
            uint32_t af[4][4], bf[4][2];
            #pragma unroll
            for (int mt=0; mt<4; mt++)
                ldsm4(af[mt][0], af[mt][1], af[mt][2], af[mt][3],
                      Ab + (aoff + mt*16*72 + ks*16)*2);
            #pragma unroll
            for (int p=0; p<2; p++)
                ldsm4(bf[2*p][0], bf[2*p][1], bf[2*p+1][0], bf[2*p+1][1],
                      Bb + (boff + p*16*72 + ks*16)*2);
            #pragma unroll
            for (int mt=0; mt<4; mt++)
                #pragma unroll
                for (int nt=0; nt<4; nt++)
                    mma16h(acc[mt][nt], af[mt], bf[nt]);
        }
    }

    float bias0[4], bias1[4];
    #pragma unroll
    for (int nt=0; nt<4; nt++){
        int n = bn + wn*32 + nt*8 + lc*2;
        bias0[nt] = biasg[n]; bias1[nt] = biasg[n+1];
    }

    #pragma unroll
    for (int mt=0; mt<4; mt++)
    #pragma unroll
    for (int hf=0; hf<2; hf++){
        const int m = bm + wm*64 + mt*16 + hf*8 + lr;
        float* dst = Cg + (size_t)m*EMB;
        #pragma unroll
        for (int nt=0; nt<4; nt++){
            const int n = bn + wn*32 + nt*8 + lc*2;
            *(float2*)&dst[n] = make_float2(acc[mt][nt][hf*2] + bias0[nt],
                                            acc[mt][nt][hf*2+1] + bias1[nt]);
        }
    }
}

__device__ __forceinline__ void avg_body(float* __restrict__ avg_out, int bid)
{
    // block = (b, q); thread handles 8 consecutive k (one chunk region)
    const int b = bid >> 11, q = bid & 2047;
    const int t = threadIdx.x;
    const int k0 = t * 8, kch = t >> 3;

    float acc[8];
    #pragma unroll
    for (int i=0;i<8;i++) acc[i] = 0.f;

    #pragma unroll 1
    for (int hb = 0; hb < NH; hb += 4) {
        uint4 pv[4]; float corr[4];
        #pragma unroll
        for (int j=0;j<4;j++){
            const int bh = b*NH + hb + j;
            float mrun = g_mrun[((size_t)bh*NCH + kch)*TGT + q];
            float sx   = g_statx[(size_t)bh*TGT + q];
            corr[j] = exp2f(mrun - sx);
            pv[j] = *(const uint4*)&g_Ph[((size_t)bh*TGT + q)*TGT + k0];
        }
        #pragma unroll
        for (int j=0;j<4;j++){
            float2 f0 = __half22float2(*(__half2*)&pv[j].x);
            float2 f1 = __half22float2(*(__half2*)&pv[j].y);
            float2 f2 = __half22float2(*(__half2*)&pv[j].z);
            float2 f3 = __half22float2(*(__half2*)&pv[j].w);
            acc[0] = fmaf(corr[j], f0.x, acc[0]);
            acc[1] = fmaf(corr[j], f0.y, acc[1]);
            acc[2] = fmaf(corr[j], f1.x, acc[2]);
            acc[3] = fmaf(corr[j], f1.y, acc[3]);
            acc[4] = fmaf(corr[j], f2.x, acc[4]);
            acc[5] = fmaf(corr[j], f2.y, acc[5]);
            acc[6] = fmaf(corr[j], f3.x, acc[6]);
            acc[7] = fmaf(corr[j], f3.y, acc[7]);
        }
    }

    const float invH = 1.0f / NH;
    float* dst = avg_out + ((size_t)b*TGT + q)*TGT + k0;
    float4 o0 = make_float4(acc[0]*invH, acc[1]*invH, acc[2]*invH, acc[3]*invH);
    float4 o1 = make_float4(acc[4]*invH, acc[5]*invH, acc[6]*invH, acc[7]*invH);
    *(float4*)(dst)     = o0;
    *(float4*)(dst + 4) = o1;
}

__global__ __launch_bounds__(256, 2)
void tail_k(float* __restrict__ attn_out, const float* __restrict__ b_out,
            float* __restrict__ avg_out)
{
    const int bid = blockIdx.x;
    if (bid < 256) outproj_body(attn_out, b_out, bid);
    else           avg_body(avg_out, bid - 256);
}

// ---------------------------------------------------------------------------
extern "C" void kernel_launch(void* const* d_in, const int* in_sizes, int n_in,
                              void* d_out, int out_size)
{
    const float* query = (const float*)d_in[0];
    const float* w_in  = (const float*)d_in[1];
    const float* b_in  = (const float*)d_in[2];
    const float* w_out = (const float*)d_in[3];
    const float* b_out = (const float*)d_in[4];

    float* out      = (float*)d_out;
    float* attn_out = out;                           // [T,B,E]
    float* avg_out  = out + (size_t)TGT*NBSZ*EMB;    // [B,T,T]

    cudaFuncSetAttribute(qkv_gemm,     cudaFuncAttributeMaxDynamicSharedMemorySize, GEMM_SMEM_BYTES);
    cudaFuncSetAttribute(flash_attn_k, cudaFuncAttributeMaxDynamicSharedMemorySize, FA_SMEM_BYTES);
    cudaFuncSetAttribute(tail_k,       cudaFuncAttributeMaxDynamicSharedMemorySize, TAIL_SMEM_BYTES);

    __half* d_qh;  cudaGetSymbolAddress((void**)&d_qh,  g_qh);
    __half* d_wih; cudaGetSymbolAddress((void**)&d_wih, g_wih);
    __half* d_woh; cudaGetSymbolAddress((void**)&d_woh, g_woh);

    // 0. fp32 -> fp16 convert
    {
        int total = MROWS*EMB/4 + 3*EMB*EMB/4 + EMB*EMB/4;
        preconv_all_k<<<(total+255)/256, 256>>>(
            (const float4*)query, (const float4*)w_in, (const float4*)w_out,
            (uint2*)d_qh, (uint2*)d_wih, (uint2*)d_woh);
    }

    // 1. QKV projection
    qkv_gemm<<<dim3(3*EMB/128, MROWS/128), 256, GEMM_SMEM_BYTES>>>(b_in);

    // 2. Flash attention (+ P / m_run / statx stores)
    flash_attn_k<<<dim3(TGT/128, NBH), 256, FA_SMEM_BYTES>>>();

    // 3. Tail: out-projection (256 blocks) || avg reduction (4096 blocks)
    tail_k<<<256 + 4096, 256, TAIL_SMEM_BYTES>>>(attn_out, b_out, avg_out);
}

// round 17
// speedup vs baseline: 1.0449x; 1.0449x over previous
#include <cuda_runtime.h>
#include <cuda_fp16.h>
#include <cstdint>
#include <math.h>

#define TGT   2048
#define NBSZ  2
#define EMB   1024
#define NH    16
#define HD    64
#define NBH   (NBSZ*NH)      // 32
#define MROWS (TGT*NBSZ)     // 4096

// ---------------- scratch (device globals, all fp16 operands) ---------------
static __device__ __half g_Qh [(size_t)NBH*TGT*HD];     // pre-scaled
static __device__ __half g_Kh [(size_t)NBH*TGT*HD];
static __device__ __half g_Vh [(size_t)NBH*TGT*HD];     // [bh][t][d] row-major
static __device__ __half g_attnh[(size_t)MROWS*EMB];
static __device__ float2 g_stats[(size_t)NBH*TGT];      // (rowmax, 1/rowsum)
static __device__ __half g_qh [(size_t)MROWS*EMB];
static __device__ __half g_wih[(size_t)3*EMB*EMB];
static __device__ __half g_woh[(size_t)EMB*EMB];

// ---------------- helpers ---------------------------------------------------
__device__ __forceinline__ uint32_t pack_h2(float hi, float lo){
    uint32_t r; asm("cvt.rn.f16x2.f32 %0, %1, %2;" : "=r"(r) : "f"(hi), "f"(lo));
    return r;
}
__device__ __forceinline__ void mma16h(float* c, const uint32_t* a, const uint32_t* b){
    asm volatile("mma.sync.aligned.m16n8k16.row.col.f32.f16.f16.f32 "
        "{%0,%1,%2,%3}, {%4,%5,%6,%7}, {%8,%9}, {%0,%1,%2,%3};"
        : "+f"(c[0]), "+f"(c[1]), "+f"(c[2]), "+f"(c[3])
        : "r"(a[0]), "r"(a[1]), "r"(a[2]), "r"(a[3]), "r"(b[0]), "r"(b[1]));
}
__device__ __forceinline__ void ldsm4(uint32_t& r0, uint32_t& r1, uint32_t& r2,
                                      uint32_t& r3, uint32_t addr){
    asm volatile("ldmatrix.sync.aligned.m8n8.x4.shared.b16 {%0,%1,%2,%3}, [%4];"
        : "=r"(r0), "=r"(r1), "=r"(r2), "=r"(r3) : "r"(addr));
}
__device__ __forceinline__ void ldsm4t(uint32_t& r0, uint32_t& r1, uint32_t& r2,
                                       uint32_t& r3, uint32_t addr){
    asm volatile("ldmatrix.sync.aligned.m8n8.x4.trans.shared.b16 {%0,%1,%2,%3}, [%4];"
        : "=r"(r0), "=r"(r1), "=r"(r2), "=r"(r3) : "r"(addr));
}
__device__ __forceinline__ uint32_t smem_u32(const void* p){
    uint32_t a; asm("{ .reg .u64 t; cvta.to.shared.u64 t, %1; cvt.u32.u64 %0, t; }":"=r"(a):"l"(p));
    return a;
}
__device__ __forceinline__ void cpa16(uint32_t s, const void* g){
    asm volatile("cp.async.cg.shared.global [%0], [%1], 16;" :: "r"(s), "l"(g) : "memory");
}
#define CP_COMMIT() asm volatile("cp.async.commit_group;" ::: "memory")
#define CP_WAIT(n)  asm volatile("cp.async.wait_group %0;" :: "n"(n) : "memory")

#define LDSM_H_A(j, rowbase, stride) \
    ((((rowbase) + (((j)>>3)&1)*8 + ((j)&7))*(stride)) + (((j)>>4)*8))
#define LDSM_H_B(j, rowbase, stride) \
    ((((rowbase) + (((j)>>4)*8) + ((j)&7))*(stride)) + ((((j)>>3)&1)*8))

#define L2E 1.4426950408889634f

// ---------------- fused pre-convert fp32 -> fp16 (one launch) ---------------
__global__ void preconv_all_k(const float4* __restrict__ q,
                              const float4* __restrict__ wi,
                              const float4* __restrict__ wo,
                              uint2* __restrict__ dq,
                              uint2* __restrict__ dwi,
                              uint2* __restrict__ dwo)
{
    const int NQ = MROWS*EMB/4, NWI = 3*EMB*EMB/4, NWO = EMB*EMB/4;
    int i = blockIdx.x*blockDim.x + threadIdx.x;
    float4 v; uint2 o;
    if (i < NQ)              { v = q[i];        o.x = pack_h2(v.y, v.x); o.y = pack_h2(v.w, v.z); dq[i] = o; }
    else if (i < NQ+NWI)     { v = wi[i-NQ];    o.x = pack_h2(v.y, v.x); o.y = pack_h2(v.w, v.z); dwi[i-NQ] = o; }
    else if (i < NQ+NWI+NWO) { v = wo[i-NQ-NWI];o.x = pack_h2(v.y, v.x); o.y = pack_h2(v.w, v.z); dwo[i-NQ-NWI] = o; }
}

// ===========================================================================
// QKV GEMM (fp16): block 128x128, 256 thr, warp 64x32, BK=64, 3-stage ring.
// (validated round 14/15)
// ===========================================================================
#define GEMM_SMEM_BYTES (3*18432*2)   // 110592

__global__ __launch_bounds__(256, 2)
void qkv_gemm(const float* __restrict__ biasg)
{
    constexpr int KC = 16;
    extern __shared__ char smc[];
    const uint32_t sb = smem_u32(smc);
    const int tid = threadIdx.x, lane = tid & 31, wid = tid >> 5;
    const int wm = wid & 1, wn = wid >> 1;
    const int lr = lane >> 2, lc = lane & 3;
    const int bm = blockIdx.y * 128, bn = blockIdx.x * 128;

    const __half* A = g_qh;
    const __half* B = g_wih;

    const uint32_t aoff = LDSM_H_A(lane, wm*64, 72);
    const uint32_t boff = LDSM_H_B(lane, wn*32, 72);

    float acc[4][4][4];
    #pragma unroll
    for (int i=0;i<4;i++) for (int j=0;j<4;j++) for (int k=0;k<4;k++) acc[i][j][k]=0.f;

    auto issue = [&](int c){
        const int k0 = c*64, st = c % 3;
        const uint32_t ab = sb + st*36864;
        const uint32_t bb = ab + 18432;
        #pragma unroll
        for (int i=0;i<4;i++){
            int fi = tid + i*256, r = fi>>3, c8 = fi&7;
            cpa16(ab + (r*72 + c8*8)*2, A + (size_t)(bm+r)*EMB + k0 + c8*8);
            cpa16(bb + (r*72 + c8*8)*2, B + (size_t)(bn+r)*EMB + k0 + c8*8);
        }
        CP_COMMIT();
    };

    issue(0); issue(1);
    for (int c = 0; c < KC; c++) {
        if (c + 1 < KC) { CP_WAIT(1); } else { CP_WAIT(0); }
        __syncthreads();
        if (c + 2 < KC) issue(c+2);
        const int st = c % 3;
        const uint32_t Ab = sb + st*36864;
        const uint32_t Bb = Ab + 18432;
        #pragma unroll
        for (int ks = 0; ks < 4; ks++) {
            uint32_t af[4][4], bf[4][2];
            #pragma unroll
            for (int mt=0; mt<4; mt++)
                ldsm4(af[mt][0], af[mt][1], af[mt][2], af[mt][3],
                      Ab + (aoff + mt*16*72 + ks*16)*2);
            #pragma unroll
            for (int p=0; p<2; p++)
                ldsm4(bf[2*p][0], bf[2*p][1], bf[2*p+1][0], bf[2*p+1][1],
                      Bb + (boff + p*16*72 + ks*16)*2);
            #pragma unroll
            for (int mt=0; mt<4; mt++)
                #pragma unroll
                for (int nt=0; nt<4; nt++)
                    mma16h(acc[mt][nt], af[mt], bf[nt]);
        }
    }

    float bias0[4], bias1[4];
    #pragma unroll
    for (int nt=0; nt<4; nt++){
        int n = bn + wn*32 + nt*8 + lc*2;
        bias0[nt] = biasg[n]; bias1[nt] = biasg[n+1];
    }

    #pragma unroll
    for (int mt=0; mt<4; mt++)
    #pragma unroll
    for (int hf=0; hf<2; hf++){
        const int m = bm + wm*64 + mt*16 + hf*8 + lr;
        const int t = m >> 1, b = m & 1;
        #pragma unroll
        for (int nt=0; nt<4; nt++){
            const int n = bn + wn*32 + nt*8 + lc*2;
            float v0 = acc[mt][nt][hf*2+0] + bias0[nt];
            float v1 = acc[mt][nt][hf*2+1] + bias1[nt];
            const int which = n >> 10, e = n & 1023, h = e >> 6, d = e & 63;
            const int bh = b*NH + h;
            if (which == 0) {
                *(uint32_t*)&g_Qh[((size_t)bh*TGT + t)*HD + d] =
                    pack_h2(v1*0.125f, v0*0.125f);
            } else if (which == 1) {
                *(uint32_t*)&g_Kh[((size_t)bh*TGT + t)*HD + d] = pack_h2(v1, v0);
            } else {
                *(uint32_t*)&g_Vh[((size_t)bh*TGT + t)*HD + d] = pack_h2(v1, v0);
            }
        }
    }
}

// ===========================================================================
// Flash attention (fp16): validated round 14/15 (NO P store).
// ===========================================================================
#define FA_SMEM_BYTES (5*18432)

__global__ __launch_bounds__(256, 2)
void flash_attn_k()
{
    constexpr int NC = TGT/64;
    extern __shared__ char smc[];
    const uint32_t sb = smem_u32(smc);
    const int tid = threadIdx.x, lane = tid & 31, w = tid >> 5;
    const int lr = lane >> 2, lc = lane & 3;
    const int qt = blockIdx.x, bh = blockIdx.y;
    const int b = bh >> 4, h = bh & 15;
    const int qbase = qt * 128;

    const __half* Qg = g_Qh + (size_t)bh*TGT*HD;
    const __half* Kg = g_Kh + (size_t)bh*TGT*HD;
    const __half* Vg = g_Vh + (size_t)bh*TGT*HD;

    const uint32_t qoff = LDSM_H_A(lane, w*16, 72);
    const uint32_t koff = LDSM_H_B(lane, 0, 72);
    const uint32_t voff = LDSM_H_A(lane, 0, 72);

    auto issue_kv = [&](int kc){
        const int st = kc & 3;
        const uint32_t kb = sb + 18432 + st*18432;
        const uint32_t vb = kb + 9216;
        #pragma unroll
        for (int i=0;i<2;i++){
            int fi = tid + i*256, r = fi>>3, c8 = fi&7;
            cpa16(kb + (r*72 + c8*8)*2, Kg + (size_t)(kc*64+r)*HD + c8*8);
            cpa16(vb + (r*72 + c8*8)*2, Vg + (size_t)(kc*64+r)*HD + c8*8);
        }
        CP_COMMIT();
    };

    #pragma unroll
    for (int i=0;i<4;i++){
        int fi = tid + i*256, r = fi>>3, c8 = fi&7;
        cpa16(sb + (r*72 + c8*8)*2, Qg + (size_t)(qbase+r)*HD + c8*8);
    }
    {
        const uint32_t kb = sb + 18432, vb = kb + 9216;
        #pragma unroll
        for (int i=0;i<2;i++){
            int fi = tid + i*256, r = fi>>3, c8 = fi&7;
            cpa16(kb + (r*72 + c8*8)*2, Kg + (size_t)r*HD + c8*8);
            cpa16(vb + (r*72 + c8*8)*2, Vg + (size_t)r*HD + c8*8);
        }
        CP_COMMIT();
    }
    issue_kv(1); issue_kv(2);

    float acc_o[8][4];
    #pragma unroll
    for (int j=0;j<8;j++) for (int k=0;k<4;k++) acc_o[j][k]=0.f;
    float m_r[2] = {-1e30f,-1e30f};
    float l_r[2] = {0.f,0.f};

    const unsigned FULL = 0xffffffffu;

    for (int kc = 0; kc < NC; kc++) {
        if (kc + 2 < NC)      { CP_WAIT(2); }
        else if (kc + 1 < NC) { CP_WAIT(1); }
        else                  { CP_WAIT(0); }
        __syncthreads();
        if (kc + 3 < NC) issue_kv(kc + 3);

        const int st = kc & 3;
        const uint32_t KBu = sb + 18432 + st*18432;
        const uint32_t VBu = KBu + 9216;

        float s[8][4];
        #pragma unroll
        for (int j=0;j<8;j++) for (int k=0;k<4;k++) s[j][k]=0.f;
        #pragma unroll
        for (int ks=0; ks<4; ks++){
            uint32_t a[4], bf[8][2];
            ldsm4(a[0], a[1], a[2], a[3], sb + (qoff + ks*16)*2);
            #pragma unroll
            for (int p=0; p<4; p++)
                ldsm4(bf[2*p][0], bf[2*p][1], bf[2*p+1][0], bf[2*p+1][1],
                      KBu + (koff + p*16*72 + ks*16)*2);
            #pragma unroll
            for (int nt=0; nt<8; nt++)
                mma16h(s[nt], a, bf[nt]);
        }

        #pragma unroll
        for (int hf=0; hf<2; hf++){
            float cm = -1e30f;
            #pragma unroll
            for (int nt=0; nt<8; nt++)
                cm = fmaxf(cm, fmaxf(s[nt][hf*2], s[nt][hf*2+1]));
            cm = fmaxf(cm, __shfl_xor_sync(FULL, cm, 1));
            cm = fmaxf(cm, __shfl_xor_sync(FULL, cm, 2));
            const float mn = fmaxf(m_r[hf], cm);
            const float sc = __expf(m_r[hf] - mn);
            float cs = 0.f;
            #pragma unroll
            for (int nt=0; nt<8; nt++){
                float e0 = __expf(s[nt][hf*2]   - mn);
                float e1 = __expf(s[nt][hf*2+1] - mn);
                s[nt][hf*2] = e0; s[nt][hf*2+1] = e1;
                cs += e0 + e1;
            }
            cs += __shfl_xor_sync(FULL, cs, 1);
            cs += __shfl_xor_sync(FULL, cs, 2);
            l_r[hf] = l_r[hf]*sc + cs;
            m_r[hf] = mn;
            #pragma unroll
            for (int nt=0; nt<8; nt++){
                acc_o[nt][hf*2]   *= sc;
                acc_o[nt][hf*2+1] *= sc;
            }
        }

        #pragma unroll
        for (int ks2=0; ks2<4; ks2++){
            uint32_t a[4];
            a[0] = pack_h2(s[2*ks2  ][1], s[2*ks2  ][0]);
            a[1] = pack_h2(s[2*ks2  ][3], s[2*ks2  ][2]);
            a[2] = pack_h2(s[2*ks2+1][1], s[2*ks2+1][0]);
            a[3] = pack_h2(s[2*ks2+1][3], s[2*ks2+1][2]);
            #pragma unroll
            for (int p=0; p<4; p++){
                uint32_t b0, b1, b2, b3;
                ldsm4t(b0, b1, b2, b3, VBu + (voff + ks2*16*72 + p*16)*2);
                uint32_t bA[2] = {b0, b1}, bB[2] = {b2, b3};
                mma16h(acc_o[2*p  ], a, bA);
                mma16h(acc_o[2*p+1], a, bB);
            }
        }
    }

    #pragma unroll
    for (int hf=0; hf<2; hf++){
        const float invl = 1.0f / l_r[hf];
        const int q = qbase + w*16 + hf*8 + lr;
        __half* dst = g_attnh + ((size_t)q*NBSZ + b)*EMB + h*HD;
        #pragma unroll
        for (int nt=0; nt<8; nt++)
            *(uint32_t*)&dst[nt*8 + lc*2] =
                pack_h2(acc_o[nt][hf*2+1]*invl, acc_o[nt][hf*2]*invl);
        if (lc == 0)
            g_stats[(size_t)bh*TGT + q] = make_float2(m_r[hf], invl);
    }
}

// ===========================================================================
// Merged tail: blocks [0,256) = out-proj; [256, 256+512) = avg (128q x 128k).
// avg: Q tile loaded once per head serves 128 k-cols (Q traffic -50% vs r15).
// SMEM: outproj ring 110592 B; avg 2 stages x (Q 18432 + K 18432) = 73728 B.
// ===========================================================================
#define TAIL_SMEM_BYTES (3*18432*2)   // 110592

__device__ __forceinline__ void outproj_body(float* __restrict__ Cg,
                                             const float* __restrict__ biasg, int bid)
{
    constexpr int KC = 16;
    extern __shared__ char smc[];
    const uint32_t sb = smem_u32(smc);
    const int tid = threadIdx.x, lane = tid & 31, wid = tid >> 5;
    const int wm = wid & 1, wn = wid >> 1;
    const int lr = lane >> 2, lc = lane & 3;
    const int bm = (bid >> 3) * 128, bn = (bid & 7) * 128;

    const __half* A = g_attnh;
    const __half* B = g_woh;

    const uint32_t aoff = LDSM_H_A(lane, wm*64, 72);
    const uint32_t boff = LDSM_H_B(lane, wn*32, 72);

    float acc[4][4][4];
    #pragma unroll
    for (int i=0;i<4;i++) for (int j=0;j<4;j++) for (int k=0;k<4;k++) acc[i][j][k]=0.f;

    auto issue = [&](int c){
        const int k0 = c*64, st = c % 3;
        const uint32_t ab = sb + st*36864;
        const uint32_t bb = ab + 18432;
        #pragma unroll
        for (int i=0;i<4;i++){
            int fi = tid + i*256, r = fi>>3, c8 = fi&7;
            cpa16(ab + (r*72 + c8*8)*2, A + (size_t)(bm+r)*EMB + k0 + c8*8);
            cpa16(bb + (r*72 + c8*8)*2, B + (size_t)(bn+r)*EMB + k0 + c8*8);
        }
        CP_COMMIT();
    };

    issue(0); issue(1);
    for (int c = 0; c < KC; c++) {
        if (c + 1 < KC) { CP_WAIT(1); } else { CP_WAIT(0); }
        __syncthreads();
        if (c + 2 < KC) issue(c+2);
        const int st = c % 3;
        const uint32_t Ab = sb + st*36864;
        const uint32_t Bb = Ab + 18432;
        #pragma unroll
        for (int ks = 0; ks < 4; ks++) {
            uint32_t af[4][4], bf[4][2];
            #pragma unroll
            for (int mt=0; mt<4; mt++)
                ldsm4(af[mt][0], af[mt][1], af[mt][2], af[mt][3],
                      Ab + (aoff + mt*16*72 + ks*16)*2);
            #pragma unroll
            for (int p=0; p<2; p++)
                ldsm4(bf[2*p][0], bf[2*p][1], bf[2*p+1][0], bf[2*p+1][1],
                      Bb + (boff + p*16*72 + ks*16)*2);
            #pragma unroll
            for (int mt=0; mt<4; mt++)
                #pragma unroll
                for (int nt=0; nt<4; nt++)
                    mma16h(acc[mt][nt], af[mt], bf[nt]);
        }
    }

    float bias0[4], bias1[4];
    #pragma unroll
    for (int nt=0; nt<4; nt++){
        int n = bn + wn*32 + nt*8 + lc*2;
        bias0[nt] = biasg[n]; bias1[nt] = biasg[n+1];
    }

    #pragma unroll
    for (int mt=0; mt<4; mt++)
    #pragma unroll
    for (int hf=0; hf<2; hf++){
        const int m = bm + wm*64 + mt*16 + hf*8 + lr;
        float* dst = Cg + (size_t)m*EMB;
        #pragma unroll
        for (int nt=0; nt<4; nt++){
            const int n = bn + wn*32 + nt*8 + lc*2;
            *(float2*)&dst[n] = make_float2(acc[mt][nt][hf*2] + bias0[nt],
                                            acc[mt][nt][hf*2+1] + bias1[nt]);
        }
    }
}

__device__ __forceinline__ void avg_body(float* __restrict__ avg_out, int bid)
{
    // 512 blocks: b = bid>>8, qt = (bid>>4)&15, kt = bid&15 (128-wide k tile)
    extern __shared__ char smc[];
    const uint32_t sb = smem_u32(smc);
    const int tid = threadIdx.x, lane = tid & 31, wid = tid >> 5;
    const int wm = wid & 3, wn = wid >> 2;          // 4(q, 32 rows) x 2(k, 64 cols)
    const int lr = lane >> 2, lc = lane & 3;
    const int b = bid >> 8, qt = (bid >> 4) & 15, kt = bid & 15;

    const uint32_t aoff = LDSM_H_A(lane, wm*32, 72);
    const uint32_t boff = LDSM_H_B(lane, wn*64, 72);

    auto issue_qk = [&](int h){
        const int st = h & 1;
        const int bh = b*NH + h;
        const __half* Qg = g_Qh + (size_t)bh*TGT*HD;
        const __half* Kg = g_Kh + (size_t)bh*TGT*HD;
        const uint32_t qb = sb + st*36864;
        const uint32_t kb = qb + 18432;
        #pragma unroll
        for (int i=0;i<4;i++){
            int fi = tid + i*256, r = fi>>3, c8 = fi&7;
            cpa16(qb + (r*72 + c8*8)*2, Qg + (size_t)(qt*128+r)*HD + c8*8);
            cpa16(kb + (r*72 + c8*8)*2, Kg + (size_t)(kt*128+r)*HD + c8*8);
        }
        CP_COMMIT();
    };

    float acc[2][2][4][4];   // [knt2][mt][nt][c]
    #pragma unroll
    for (int a=0;a<2;a++) for (int i=0;i<2;i++)
        for (int j=0;j<4;j++) for (int k=0;k<4;k++) acc[a][i][j][k]=0.f;

    issue_qk(0);
    for (int h = 0; h < NH; h++) {
        CP_WAIT(0);
        __syncthreads();
        if (h + 1 < NH) issue_qk(h+1);
        const int st = h & 1;
        const uint32_t QBu = sb + st*36864;
        const uint32_t KBu = QBu + 18432;

        const int bh = b*NH + h;
        float crow[2][2];
        #pragma unroll
        for (int mt=0; mt<2; mt++)
        #pragma unroll
        for (int hf=0; hf<2; hf++){
            const int q = qt*128 + wm*32 + mt*16 + hf*8 + lr;
            const float2 st2 = g_stats[(size_t)bh*TGT + q];
            crow[mt][hf] = __log2f(st2.y) - st2.x * L2E;
        }

        #pragma unroll
        for (int knt2 = 0; knt2 < 2; knt2++) {
            float s[2][4][4];
            #pragma unroll
            for (int i=0;i<2;i++) for (int j=0;j<4;j++) for (int k=0;k<4;k++) s[i][j][k]=0.f;
            #pragma unroll
            for (int ks=0; ks<4; ks++){
                uint32_t af[2][4], bf[4][2];
                #pragma unroll
                for (int mt=0; mt<2; mt++)
                    ldsm4(af[mt][0], af[mt][1], af[mt][2], af[mt][3],
                          QBu + (aoff + mt*16*72 + ks*16)*2);
                #pragma unroll
                for (int p=0; p<2; p++)
                    ldsm4(bf[2*p][0], bf[2*p][1], bf[2*p+1][0], bf[2*p+1][1],
                          KBu + (boff + (knt2*32 + p*16)*72 + ks*16)*2);
                #pragma unroll
                for (int mt=0; mt<2; mt++)
                    #pragma unroll
                    for (int nt=0; nt<4; nt++)
                        mma16h(s[mt][nt], af[mt], bf[nt]);
            }

            #pragma unroll
            for (int mt=0; mt<2; mt++)
            #pragma unroll
            for (int hf=0; hf<2; hf++){
                const float c = crow[mt][hf];
                #pragma unroll
                for (int nt=0; nt<4; nt++){
                    acc[knt2][mt][nt][hf*2]   += exp2f(fmaf(s[mt][nt][hf*2],   L2E, c));
                    acc[knt2][mt][nt][hf*2+1] += exp2f(fmaf(s[mt][nt][hf*2+1], L2E, c));
                }
            }
        }
    }

    const float invH = 1.0f / NH;
    #pragma unroll
    for (int knt2=0; knt2<2; knt2++)
    #pragma unroll
    for (int mt=0; mt<2; mt++)
    #pragma unroll
    for (int hf=0; hf<2; hf++){
        const int q = qt*128 + wm*32 + mt*16 + hf*8 + lr;
        float* dst = avg_out + ((size_t)b*TGT + q)*TGT + kt*128 + wn*64 + knt2*32;
        #pragma unroll
        for (int nt=0; nt<4; nt++)
            *(float2*)(dst + nt*8 + lc*2) =
                make_float2(acc[knt2][mt][nt][hf*2]*invH, acc[knt2][mt][nt][hf*2+1]*invH);
    }
}

__global__ __launch_bounds__(256, 2)
void tail_k(float* __restrict__ attn_out, const float* __restrict__ b_out,
            float* __restrict__ avg_out)
{
    const int bid = blockIdx.x;
    if (bid < 256) outproj_body(attn_out, b_out, bid);
    else           avg_body(avg_out, bid - 256);
}

// ---------------------------------------------------------------------------
extern "C" void kernel_launch(void* const* d_in, const int* in_sizes, int n_in,
                              void* d_out, int out_size)
{
    const float* query = (const float*)d_in[0];
    const float* w_in  = (const float*)d_in[1];
    const float* b_in  = (const float*)d_in[2];
    const float* w_out = (const float*)d_in[3];
    const float* b_out = (const float*)d_in[4];

    float* out      = (float*)d_out;
    float* attn_out = out;                           // [T,B,E]
    float* avg_out  = out + (size_t)TGT*NBSZ*EMB;    // [B,T,T]

    cudaFuncSetAttribute(qkv_gemm,     cudaFuncAttributeMaxDynamicSharedMemorySize, GEMM_SMEM_BYTES);
    cudaFuncSetAttribute(flash_attn_k, cudaFuncAttributeMaxDynamicSharedMemorySize, FA_SMEM_BYTES);
    cudaFuncSetAttribute(tail_k,       cudaFuncAttributeMaxDynamicSharedMemorySize, TAIL_SMEM_BYTES);

    __half* d_qh;  cudaGetSymbolAddress((void**)&d_qh,  g_qh);
    __half* d_wih; cudaGetSymbolAddress((void**)&d_wih, g_wih);
    __half* d_woh; cudaGetSymbolAddress((void**)&d_woh, g_woh);

    // 0. fp32 -> fp16 convert (single launch)
    {
        int total = MROWS*EMB/4 + 3*EMB*EMB/4 + EMB*EMB/4;
        preconv_all_k<<<(total+255)/256, 256>>>(
            (const float4*)query, (const float4*)w_in, (const float4*)w_out,
            (uint2*)d_qh, (uint2*)d_wih, (uint2*)d_woh);
    }

    // 1. QKV projection
    qkv_gemm<<<dim3(3*EMB/128, MROWS/128), 256, GEMM_SMEM_BYTES>>>(b_in);

    // 2. Flash attention (no P store — critical path kept minimal)
    flash_attn_k<<<dim3(TGT/128, NBH), 256, FA_SMEM_BYTES>>>();

    // 3. Tail: out-proj (256 blocks, first wave) || avg 128x128 (512 blocks)
    tail_k<<<256 + 512, 256, TAIL_SMEM_BYTES>>>(attn_out, b_out, avg_out);
}